// round 10
// baseline (speedup 1.0000x reference)
#include <cuda_runtime.h>
#include <math.h>

#define FULL 0xffffffffu
typedef unsigned long long ull;

// Problem constants
constexpr int B_ = 4;
constexpr int P_ = 2048;
constexpr int NPOS = B_ * P_;           // 8192
constexpr int NCHUNK = 64;              // 32-position chunks per sequence

// Scratch (device globals; no allocation in kernel_launch)
__device__ float g_enc_psi[NPOS * 32];
__device__ float g_enc[NPOS * 32];
__device__ float g_u[NPOS * 4];
__device__ float g_num[NPOS * 4 * 32];
__device__ float g_den[NPOS * 4];
__device__ float g_ct2[B_ * NCHUNK * 32];       // chunk totals of enc_psi
__device__ float g_ct4n[16 * NCHUNK * 32];      // chunk totals of u*enc per (b,h)
__device__ float g_ct4d[16 * NCHUNK];           // chunk totals of u per (b,h)

// ---- f32x2 packed helpers (sm_103a FFMA2 path) ------------------------------
__device__ __forceinline__ ull pack2(float x, float y) {
    ull r; asm("mov.b64 %0, {%1, %2};" : "=l"(r) : "f"(x), "f"(y)); return r;
}
__device__ __forceinline__ void unpack2(ull v, float& x, float& y) {
    asm("mov.b64 {%0, %1}, %2;" : "=f"(x), "=f"(y) : "l"(v));
}
__device__ __forceinline__ ull ffma2(ull a, ull b, ull c) {
    ull d; asm("fma.rn.f32x2 %0, %1, %2, %3;" : "=l"(d) : "l"(a), "l"(b), "l"(c));
    return d;
}

// combined[lane] for one position
__device__ __forceinline__ float combined_lane(float t, float v, int m, int lane) {
    if (lane < 8) {
        float sc;
        switch (lane >> 1) {
            case 0:  sc = 1.0f;   break;
            case 1:  sc = 0.1f;   break;
            case 2:  sc = 0.01f;  break;
            default: sc = 0.001f; break;
        }
        float r = t * sc;
        return (lane & 1) ? cosf(r) : sinf(r);
    } else if (lane == 8) {
        return v;
    } else if (lane < 31) {
        return (m == lane - 8) ? 1.0f : 0.0f;
    }
    return 0.0f;
}

// ---------------------------------------------------------------------------
// K1: features + psi MLP + phi MLP + enc_psi chunk totals.
// Grid 256 (block = one 32-position chunk) x 256 threads; warp = 4 positions.
// ---------------------------------------------------------------------------
__global__ __launch_bounds__(256) void k1_feat_mlps(
    const float* __restrict__ times, const float* __restrict__ values,
    const int* __restrict__ meas, const float* __restrict__ mask,
    const float* __restrict__ pw1, const float* __restrict__ pb1,
    const float* __restrict__ pw2, const float* __restrict__ pb2,
    const float* __restrict__ fw1, const float* __restrict__ fb1,
    const float* __restrict__ fw2, const float* __restrict__ fb2)
{
    __shared__ float4 s_pw1[8 * 32], s_pw2[8 * 32];
    __shared__ float4 s_fw1[8 * 32], s_fw2[8 * 32];
    __shared__ float  s_pb1[32], s_pb2[32], s_fb1[32], s_fb2[32];
    __shared__ float4 s_x4[8][4][8];
    __shared__ float4 s_h4[8][4][8];
    __shared__ float  s_part[8][32];     // per-warp enc_psi partial sums

    int tid = threadIdx.x;
    for (int i = tid; i < 8 * 32; i += 256) {
        int i4 = i >> 5, l = i & 31, r0 = i4 * 4;
        float p3 = (r0 + 3 < 31) ? pw1[(r0 + 3) * 32 + l] : 0.0f;
        float f3 = (r0 + 3 < 31) ? fw1[(r0 + 3) * 32 + l] : 0.0f;
        s_pw1[i] = make_float4(pw1[r0 * 32 + l], pw1[(r0 + 1) * 32 + l],
                               pw1[(r0 + 2) * 32 + l], p3);
        s_fw1[i] = make_float4(fw1[r0 * 32 + l], fw1[(r0 + 1) * 32 + l],
                               fw1[(r0 + 2) * 32 + l], f3);
        s_pw2[i] = make_float4(pw2[r0 * 32 + l], pw2[(r0 + 1) * 32 + l],
                               pw2[(r0 + 2) * 32 + l], pw2[(r0 + 3) * 32 + l]);
        s_fw2[i] = make_float4(fw2[r0 * 32 + l], fw2[(r0 + 1) * 32 + l],
                               fw2[(r0 + 2) * 32 + l], fw2[(r0 + 3) * 32 + l]);
    }
    if (tid < 32) { s_pb1[tid] = pb1[tid]; s_pb2[tid] = pb2[tid];
                    s_fb1[tid] = fb1[tid]; s_fb2[tid] = fb2[tid]; }
    __syncthreads();

    int lane = tid & 31;
    int w    = tid >> 5;
    int pos0 = blockIdx.x * 32 + w * 4;
    int b    = blockIdx.x >> 6;
    int chunk = blockIdx.x & 63;

    float mk[4];
    #pragma unroll
    for (int q = 0; q < 4; q++) {
        int pos = pos0 + q;
        float t = times[pos], v = values[pos];
        mk[q] = mask[pos];
        int m = meas[pos];
        ((float*)&s_x4[w][q])[lane] = combined_lane(t, v, m, lane) * mk[q];
    }
    __syncwarp();

    float acc[4];

    // psi layer 1
    #pragma unroll
    for (int q = 0; q < 4; q++) acc[q] = s_pb1[lane];
    #pragma unroll
    for (int i4 = 0; i4 < 8; i4++) {
        float4 wv = s_pw1[i4 * 32 + lane];
        #pragma unroll
        for (int q = 0; q < 4; q++) {
            float4 xv = s_x4[w][q][i4];
            acc[q] += xv.x * wv.x; acc[q] += xv.y * wv.y;
            acc[q] += xv.z * wv.z; acc[q] += xv.w * wv.w;
        }
    }
    #pragma unroll
    for (int q = 0; q < 4; q++)
        ((float*)&s_h4[w][q])[lane] = fmaxf(acc[q], 0.0f) * mk[q];
    __syncwarp();

    // psi layer 2 (+ chunk partial)
    #pragma unroll
    for (int q = 0; q < 4; q++) acc[q] = s_pb2[lane];
    #pragma unroll
    for (int i4 = 0; i4 < 8; i4++) {
        float4 wv = s_pw2[i4 * 32 + lane];
        #pragma unroll
        for (int q = 0; q < 4; q++) {
            float4 xv = s_h4[w][q][i4];
            acc[q] += xv.x * wv.x; acc[q] += xv.y * wv.y;
            acc[q] += xv.z * wv.z; acc[q] += xv.w * wv.w;
        }
    }
    float psum = 0.0f;
    #pragma unroll
    for (int q = 0; q < 4; q++) {
        float ev = fmaxf(acc[q], 0.0f) * mk[q];
        g_enc_psi[(pos0 + q) * 32 + lane] = ev;
        psum += ev;
    }
    s_part[w][lane] = psum;
    __syncwarp();

    // phi layer 1
    #pragma unroll
    for (int q = 0; q < 4; q++) acc[q] = s_fb1[lane];
    #pragma unroll
    for (int i4 = 0; i4 < 8; i4++) {
        float4 wv = s_fw1[i4 * 32 + lane];
        #pragma unroll
        for (int q = 0; q < 4; q++) {
            float4 xv = s_x4[w][q][i4];
            acc[q] += xv.x * wv.x; acc[q] += xv.y * wv.y;
            acc[q] += xv.z * wv.z; acc[q] += xv.w * wv.w;
        }
    }
    #pragma unroll
    for (int q = 0; q < 4; q++)
        ((float*)&s_h4[w][q])[lane] = fmaxf(acc[q], 0.0f) * mk[q];
    __syncwarp();

    // phi layer 2
    #pragma unroll
    for (int q = 0; q < 4; q++) acc[q] = s_fb2[lane];
    #pragma unroll
    for (int i4 = 0; i4 < 8; i4++) {
        float4 wv = s_fw2[i4 * 32 + lane];
        #pragma unroll
        for (int q = 0; q < 4; q++) {
            float4 xv = s_h4[w][q][i4];
            acc[q] += xv.x * wv.x; acc[q] += xv.y * wv.y;
            acc[q] += xv.z * wv.z; acc[q] += xv.w * wv.w;
        }
    }
    #pragma unroll
    for (int q = 0; q < 4; q++)
        g_enc[(pos0 + q) * 32 + lane] = fmaxf(acc[q], 0.0f) * mk[q];

    // chunk total of enc_psi
    __syncthreads();
    if (w == 0) {
        float t = 0.0f;
        #pragma unroll
        for (int w2 = 0; w2 < 8; w2++) t += s_part[w2][lane];
        g_ct2[(b * NCHUNK + chunk) * 32 + lane] = t;
    }
}

// ---------------------------------------------------------------------------
// K3: inline aggraw (cumsum via g_ct2 chunk offsets + within-chunk prefix),
// agg matvec, keys matvec, preattn, u, and k4 chunk totals (u*enc, u).
// Grid 256 (block = chunk) x 256 threads.
// ---------------------------------------------------------------------------
__global__ __launch_bounds__(256) void k3_preattn(
    const float* __restrict__ times, const float* __restrict__ values,
    const int* __restrict__ meas, const float* __restrict__ mask,
    const float* __restrict__ arw, const float* __restrict__ arb,
    const float* __restrict__ wk, const float* __restrict__ wq)
{
    __shared__ float4 s_ar4[8 * 32];
    __shared__ float4 s_wk4[32 * 32];
    __shared__ float  s_ab[32], s_wq[64];
    __shared__ float4 s_g4[8][4][8];
    __shared__ float2 s_y2[8][4][32];
    __shared__ float  s_wp[8][32];
    __shared__ float  s_pn[8][4][32];
    __shared__ float  s_pd[8][4];

    int tid = threadIdx.x;
    for (int i = tid; i < 8 * 32; i += 256) {
        int i4 = i >> 5, l = i & 31, r0 = i4 * 4;
        s_ar4[i] = make_float4(arw[r0 * 32 + l], arw[(r0 + 1) * 32 + l],
                               arw[(r0 + 2) * 32 + l], arw[(r0 + 3) * 32 + l]);
    }
    for (int i = tid; i < 32 * 32; i += 256) {
        int i2 = i >> 5, l = i & 31, r0 = i2 * 2;
        float w2a = (r0 + 1 < 63) ? wk[(r0 + 1) * 64 + l]      : 0.0f;
        float w2b = (r0 + 1 < 63) ? wk[(r0 + 1) * 64 + l + 32] : 0.0f;
        s_wk4[i] = make_float4(wk[r0 * 64 + l], wk[r0 * 64 + l + 32], w2a, w2b);
    }
    if (tid < 32) s_ab[tid] = arb[tid];
    if (tid < 64) s_wq[tid] = wq[tid];

    int lane  = tid & 31;
    int w     = tid >> 5;
    int b     = blockIdx.x >> 6;
    int chunk = blockIdx.x & 63;
    int pos0  = blockIdx.x * 32 + w * 4;        // global position
    int lp0   = chunk * 32 + w * 4;             // LOCAL (within-sequence) position

    // Stage raw combined; load own-chunk enc_psi; within-warp prefix.
    float mk[4], cq[4];
    {
        float eq[4];
        #pragma unroll
        for (int q = 0; q < 4; q++) {
            int pos = pos0 + q;
            float t = times[pos], v = values[pos];
            mk[q] = mask[pos];
            int m = meas[pos];
            ((float*)s_y2[w][q])[lane] = combined_lane(t, v, m, lane);
            eq[q] = g_enc_psi[pos * 32 + lane];
        }
        cq[0] = eq[0];
        cq[1] = cq[0] + eq[1];
        cq[2] = cq[1] + eq[2];
        cq[3] = cq[2] + eq[3];
        s_wp[w][lane] = cq[3];
    }
    __syncthreads();   // covers weights, s_y2 low, s_wp

    // exclusive offset: preceding chunks (g_ct2) + preceding warps
    float off;
    {
        const float* ct = g_ct2 + (b * NCHUNK) * 32 + lane;
        float o0 = 0.f, o1 = 0.f, o2 = 0.f, o3 = 0.f;
        int k = 0;
        for (; k + 4 <= chunk; k += 4) {
            o0 += ct[k * 32];       o1 += ct[(k + 1) * 32];
            o2 += ct[(k + 2) * 32]; o3 += ct[(k + 3) * 32];
        }
        for (; k < chunk; k++) o0 += ct[k * 32];
        off = (o0 + o1) + (o2 + o3);
    }
    #pragma unroll
    for (int w2 = 0; w2 < 8; w2++)
        if (w2 < w) off += s_wp[w2][lane];

    // aggraw = cumsum / (LOCAL count) * mask -> staged for broadcast matvec
    #pragma unroll
    for (int q = 0; q < 4; q++) {
        float cum = off + cq[q];
        float agr = __fdividef(cum, (float)(lp0 + q + 1)) * mk[q];
        ((float*)&s_g4[w][q])[lane] = agr;
    }
    __syncwarp();

    // agg matvec (32x32)
    float agg[4];
    #pragma unroll
    for (int q = 0; q < 4; q++) agg[q] = s_ab[lane];
    #pragma unroll
    for (int i4 = 0; i4 < 8; i4++) {
        float4 wv = s_ar4[i4 * 32 + lane];
        #pragma unroll
        for (int q = 0; q < 4; q++) {
            float4 xv = s_g4[w][q][i4];
            agg[q] += xv.x * wv.x; agg[q] += xv.y * wv.y;
            agg[q] += xv.z * wv.z; agg[q] += xv.w * wv.w;
        }
    }
    #pragma unroll
    for (int q = 0; q < 4; q++) {
        ((float*)s_y2[w][q])[31 + lane] = agg[q] * mk[q];
        if (lane == 0) ((float*)s_y2[w][q])[63] = 0.0f;
    }
    __syncwarp();

    // keys matvec (63x64)
    float a0[4] = {0.f, 0.f, 0.f, 0.f}, a1[4] = {0.f, 0.f, 0.f, 0.f};
    #pragma unroll
    for (int i2 = 0; i2 < 32; i2++) {
        float4 wv = s_wk4[i2 * 32 + lane];
        #pragma unroll
        for (int q = 0; q < 4; q++) {
            float2 yv = s_y2[w][q][i2];
            a0[q] += yv.x * wv.x; a1[q] += yv.x * wv.y;
            a0[q] += yv.y * wv.z; a1[q] += yv.y * wv.w;
        }
    }

    int hh = lane & 3, dd = lane >> 2;
    float q0 = s_wq[hh * 16 + dd], q1 = s_wq[hh * 16 + dd + 8];
    float ufull[4];
    #pragma unroll
    for (int q = 0; q < 4; q++) {
        float part = a0[q] * mk[q] * q0 + a1[q] * mk[q] * q1;
        part += __shfl_xor_sync(FULL, part, 4);
        part += __shfl_xor_sync(FULL, part, 8);
        part += __shfl_xor_sync(FULL, part, 16);
        float pre = part * 0.25f * mk[q];
        ufull[q] = expf(pre);                    // lane l holds head l&3
        if (lane < 4) g_u[(pos0 + q) * 4 + lane] = ufull[q];
    }

    // k4 chunk totals: pn[h][lane] = sum_q u[q][h]*enc[q][lane]; pd[h] = sum_q u[q][h]
    {
        float e2q[4];
        #pragma unroll
        for (int q = 0; q < 4; q++) e2q[q] = g_enc[(pos0 + q) * 32 + lane];
        #pragma unroll
        for (int h = 0; h < 4; h++) {
            float s = 0.0f;
            #pragma unroll
            for (int q = 0; q < 4; q++)
                s += __shfl_sync(FULL, ufull[q], h) * e2q[q];
            s_pn[w][h][lane] = s;
        }
        if (lane < 4)
            s_pd[w][lane] = ufull[0] + ufull[1] + ufull[2] + ufull[3];
    }
    __syncthreads();

    if (w < 4) {
        int h = w;
        float t = 0.0f;
        #pragma unroll
        for (int w2 = 0; w2 < 8; w2++) t += s_pn[w2][h][lane];
        g_ct4n[((b * 4 + h) * NCHUNK + chunk) * 32 + lane] = t;
        if (lane == 0) {
            float td = 0.0f;
            #pragma unroll
            for (int w2 = 0; w2 < 8; w2++) td += s_pd[w2][h];
            g_ct4d[(b * 4 + h) * NCHUNK + chunk] = td;
        }
    }
}

// ---------------------------------------------------------------------------
// K4b: pure offset + write. One warp per (b,h,chunk) = 1024 warps = 128
// blocks x 256 threads. Offset from precomputed chunk totals (balanced,
// coalesced); write pass is a register-only 32-step chain.
// ---------------------------------------------------------------------------
__global__ __launch_bounds__(256) void k4_scan()
{
    int tid  = threadIdx.x;
    int lane = tid & 31;
    int w    = tid >> 5;
    int wg   = blockIdx.x * 8 + w;       // 0..1023
    int bh   = wg >> 6;
    int c    = wg & 63;
    int b    = bh >> 2, h = bh & 3;

    // num offset: sum of preceding chunk totals (coalesced)
    float offn;
    {
        const float* ct = g_ct4n + (bh * NCHUNK) * 32 + lane;
        float o0 = 0.f, o1 = 0.f, o2 = 0.f, o3 = 0.f;
        int k = 0;
        for (; k + 4 <= c; k += 4) {
            o0 += ct[k * 32];       o1 += ct[(k + 1) * 32];
            o2 += ct[(k + 2) * 32]; o3 += ct[(k + 3) * 32];
        }
        for (; k < c; k++) o0 += ct[k * 32];
        offn = (o0 + o1) + (o2 + o3);
    }
    // den offset: lanes cover chunk indices, xor-reduce
    float offd;
    {
        const float* cd = g_ct4d + bh * NCHUNK;
        float myd = 0.0f;
        if (lane < c)      myd  = cd[lane];
        if (lane + 32 < c) myd += cd[lane + 32];
        #pragma unroll
        for (int o = 16; o >= 1; o >>= 1) myd += __shfl_xor_sync(FULL, myd, o);
        offd = myd;
    }

    const float* up = g_u   + b * P_ * 4 + h;
    const float* ep = g_enc + b * P_ * 32 + lane;
    int p0 = c * 32;

    float uv[32], vals[32];
    #pragma unroll
    for (int j = 0; j < 32; j++) uv[j] = up[(p0 + j) * 4];
    #pragma unroll
    for (int j = 0; j < 32; j++) vals[j] = uv[j] * ep[(p0 + j) * 32];

    float* nq = g_num + (b * P_ * 4 + h) * 32 + lane;
    float* dq = g_den + b * P_ * 4 + h;

    float accn = offn, accu = offd;
    #pragma unroll
    for (int j = 0; j < 32; j++) {
        int p = p0 + j;
        accn += vals[j];
        accu += uv[j];
        nq[p * 128] = accn;
        if (lane == 0) dq[p * 4] = accu;
    }
}

// ---------------------------------------------------------------------------
// K5 v3: rho MLP with POSITION-PAIR f32x2 packing.
// acc2 = (out[q], out[q+1]); a2 = (a[q][k], a[q+1][k]) loaded once via
// BROADCAST LDS (1 wavefront); weights pre-duplicated in smem:
// (w[k][l], w[k][l], w[k][l+32], w[k][l+32]) -> 1 per-lane LDS.128 per k
// feeds 8 FFMA2. Crossbar per k: 6 cyc vs 36 before.
// Grid 128 x 256 threads (8 warps), warp = 8 positions (4 pairs). 144KB smem.
// ---------------------------------------------------------------------------
__global__ __launch_bounds__(256) void k5_rho(
    const float* __restrict__ mask,
    const float* __restrict__ rw1, const float* __restrict__ rb1,
    const float* __restrict__ rw2, const float* __restrict__ rb2,
    float* __restrict__ out)
{
    extern __shared__ char sm5[];
    float4* s_w1d = (float4*)sm5;                   // 128k x 32 lanes = 64KB
    float4* s_w2d = (float4*)(sm5 + 65536);         // 64k x 32 = 32KB
    ull*    s_a   = (ull*)   (sm5 + 98304);         // [8w][128k][4qp] = 32KB
    ull*    s_h   = (ull*)   (sm5 + 131072);        // [8w][64k][4qp] = 16KB

    int tid = threadIdx.x;
    int w = tid >> 5, lane = tid & 31;

    // Stage duplicated weights: (w[k][l], w[k][l], w[k][l+32], w[k][l+32])
    for (int i = tid; i < 128 * 32; i += 256) {
        int k = i >> 5, l = i & 31;
        float wa = rw1[k * 64 + l], wb = rw1[k * 64 + l + 32];
        s_w1d[i] = make_float4(wa, wa, wb, wb);
    }
    for (int i = tid; i < 64 * 32; i += 256) {
        int k = i >> 5, l = i & 31;
        float wa = rw2[k * 64 + l], wb = rw2[k * 64 + l + 32];
        s_w2d[i] = make_float4(wa, wa, wb, wb);
    }

    // Stage activations as position pairs: s_a[w][k][qp] = (v[2qp][k], v[2qp+1][k])
    int pos0 = (blockIdx.x * 8 + w) * 8;
    float mks[8];
    #pragma unroll
    for (int q = 0; q < 8; q++) mks[q] = mask[pos0 + q];

    #pragma unroll
    for (int qp = 0; qp < 4; qp++) {
        int pa = pos0 + 2 * qp, pb = pa + 1;
        float ma2 = mks[2 * qp] * mks[2 * qp];
        float mb2 = mks[2 * qp + 1] * mks[2 * qp + 1];
        #pragma unroll
        for (int h4 = 0; h4 < 4; h4++) {
            float sa = __fdividef(ma2, g_den[pa * 4 + h4]);
            float sb = __fdividef(mb2, g_den[pb * 4 + h4]);
            float va = g_num[(pa * 4 + h4) * 32 + lane] * sa;
            float vb = g_num[(pb * 4 + h4) * 32 + lane] * sb;
            s_a[(w * 128 + h4 * 32 + lane) * 4 + qp] = pack2(va, vb);
        }
    }
    __syncthreads();

    // ---- layer 1: out[64] = relu(W1^T a + b1) ----
    ull accA[4], accB[4];
    {
        float b0 = rb1[lane], b1v = rb1[lane + 32];
        ull pA = pack2(b0, b0), pB = pack2(b1v, b1v);
        #pragma unroll
        for (int qp = 0; qp < 4; qp++) { accA[qp] = pA; accB[qp] = pB; }
    }

    const ulonglong2* w1v = (const ulonglong2*)s_w1d;
    #pragma unroll 4
    for (int k = 0; k < 128; k++) {
        ulonglong2 wv = w1v[k * 32 + lane];                     // (w_l dup, w_l32 dup)
        const ulonglong2* ap = (const ulonglong2*)(s_a + (w * 128 + k) * 4);
        ulonglong2 a01 = ap[0];                                 // qp0, qp1 (broadcast)
        ulonglong2 a23 = ap[1];                                 // qp2, qp3 (broadcast)
        accA[0] = ffma2(a01.x, wv.x, accA[0]); accB[0] = ffma2(a01.x, wv.y, accB[0]);
        accA[1] = ffma2(a01.y, wv.x, accA[1]); accB[1] = ffma2(a01.y, wv.y, accB[1]);
        accA[2] = ffma2(a23.x, wv.x, accA[2]); accB[2] = ffma2(a23.x, wv.y, accB[2]);
        accA[3] = ffma2(a23.y, wv.x, accA[3]); accB[3] = ffma2(a23.y, wv.y, accB[3]);
    }

    // relu + mask -> s_h[w][k][qp], k = lane and lane+32
    #pragma unroll
    for (int qp = 0; qp < 4; qp++) {
        float r0, r1; unpack2(accA[qp], r0, r1);
        r0 = fmaxf(r0, 0.0f) * mks[2 * qp];
        r1 = fmaxf(r1, 0.0f) * mks[2 * qp + 1];
        s_h[(w * 64 + lane) * 4 + qp] = pack2(r0, r1);
        unpack2(accB[qp], r0, r1);
        r0 = fmaxf(r0, 0.0f) * mks[2 * qp];
        r1 = fmaxf(r1, 0.0f) * mks[2 * qp + 1];
        s_h[(w * 64 + lane + 32) * 4 + qp] = pack2(r0, r1);
    }
    __syncwarp();

    // ---- layer 2 ----
    {
        float b0 = rb2[lane], b1v = rb2[lane + 32];
        ull pA = pack2(b0, b0), pB = pack2(b1v, b1v);
        #pragma unroll
        for (int qp = 0; qp < 4; qp++) { accA[qp] = pA; accB[qp] = pB; }
    }

    const ulonglong2* w2v = (const ulonglong2*)s_w2d;
    #pragma unroll 4
    for (int k = 0; k < 64; k++) {
        ulonglong2 wv = w2v[k * 32 + lane];
        const ulonglong2* hp = (const ulonglong2*)(s_h + (w * 64 + k) * 4);
        ulonglong2 a01 = hp[0];
        ulonglong2 a23 = hp[1];
        accA[0] = ffma2(a01.x, wv.x, accA[0]); accB[0] = ffma2(a01.x, wv.y, accB[0]);
        accA[1] = ffma2(a01.y, wv.x, accA[1]); accB[1] = ffma2(a01.y, wv.y, accB[1]);
        accA[2] = ffma2(a23.x, wv.x, accA[2]); accB[2] = ffma2(a23.x, wv.y, accB[2]);
        accA[3] = ffma2(a23.y, wv.x, accA[3]); accB[3] = ffma2(a23.y, wv.y, accB[3]);
    }

    // relu + mask -> output
    #pragma unroll
    for (int qp = 0; qp < 4; qp++) {
        int pa = pos0 + 2 * qp, pb = pa + 1;
        float r0, r1; unpack2(accA[qp], r0, r1);
        out[pa * 64 + lane] = fmaxf(r0, 0.0f) * mks[2 * qp];
        out[pb * 64 + lane] = fmaxf(r1, 0.0f) * mks[2 * qp + 1];
        unpack2(accB[qp], r0, r1);
        out[pa * 64 + lane + 32] = fmaxf(r0, 0.0f) * mks[2 * qp];
        out[pb * 64 + lane + 32] = fmaxf(r1, 0.0f) * mks[2 * qp + 1];
    }
}

// ---------------------------------------------------------------------------
extern "C" void kernel_launch(void* const* d_in, const int* in_sizes, int n_in,
                              void* d_out, int out_size)
{
    const float* times   = (const float*)d_in[0];
    const float* values  = (const float*)d_in[1];
    const int*   meas    = (const int*)  d_in[2];
    const float* mask    = (const float*)d_in[3];
    const float* psi_w1  = (const float*)d_in[4];
    const float* psi_b1  = (const float*)d_in[5];
    const float* psi_w2  = (const float*)d_in[6];
    const float* psi_b2  = (const float*)d_in[7];
    const float* arho_w  = (const float*)d_in[8];
    const float* arho_b  = (const float*)d_in[9];
    const float* W_k     = (const float*)d_in[10];
    const float* W_q     = (const float*)d_in[11];
    const float* phi_w1  = (const float*)d_in[12];
    const float* phi_b1  = (const float*)d_in[13];
    const float* phi_w2  = (const float*)d_in[14];
    const float* phi_b2  = (const float*)d_in[15];
    const float* rho_w1  = (const float*)d_in[16];
    const float* rho_b1  = (const float*)d_in[17];
    const float* rho_w2  = (const float*)d_in[18];
    const float* rho_b2  = (const float*)d_in[19];
    float* out = (float*)d_out;

    cudaFuncSetAttribute(k5_rho, cudaFuncAttributeMaxDynamicSharedMemorySize, 147456);

    k1_feat_mlps<<<256, 256>>>(times, values, meas, mask,
                               psi_w1, psi_b1, psi_w2, psi_b2,
                               phi_w1, phi_b1, phi_w2, phi_b2);
    k3_preattn<<<256, 256>>>(times, values, meas, mask,
                             arho_w, arho_b, W_k, W_q);
    k4_scan<<<128, 256>>>();
    k5_rho<<<128, 256, 147456>>>(mask, rho_w1, rho_b1, rho_w2, rho_b2, out);
}